// round 7
// baseline (speedup 1.0000x reference)
#include <cuda_runtime.h>
#include <cuda_bf16.h>
#include <math.h>
#include <stdint.h>

// ---------------- problem constants -----------------------------------------
#define TOK   1024
#define D     1024
#define HQ    2048
#define HEADS 8
#define QD    256
#define HALF  128
#define NK    32
#define DTK   4
#define NEXP  128
#define E     1024
#define O     1024
#define KDIM  1024
#define BK    32
#define NITER (KDIM / BK)

// ---------------- scratch (8.80 MB total; round-1-passing territory) ---------
__device__ __align__(256) float g_q[TOK * HQ];     // 8 MB; first 4 MB reused as eh/C
__device__ float g_sums[QD];
__device__ float g_sqs[QD];
__device__ float g_mean[QD];
__device__ float g_rstd[QD];
__device__ float g_k0n[NK * HALF];
__device__ float g_k1n[NK * HALF];
__device__ unsigned short g_idx[TOK * NEXP];       // 256 KB (expert ids < 1024)
__device__ float g_w[TOK * NEXP];                  // 512 KB

// ---------------- helpers ----------------------------------------------------
__device__ __forceinline__ uint32_t s2u(const void* p) {
    uint32_t r;
    asm("{ .reg .u64 t; cvta.to.shared.u64 t, %1; cvt.u32.u64 %0, t; }"
        : "=r"(r) : "l"(p));
    return r;
}

// ---------------- on-the-fly split-precision warp-MMA GEMM --------------------
// C[m0:+128, n0:+64] = A[M,1024] x B(^T), fp32 in/out (+bias).
// A: [M,K] K-major fp32. B: [N,K] (BT=false) or [K,N] (BT=true) fp32.
// fp32 tiles -> P bf16 planes in registers -> swizzled STATIC smem (<=48KB,
// single buffer) -> ldmatrix -> mma.sync bf16. NP plane-pair passes:
// P=2: hh,hl,lh (~4e-6). P=3: hh,hm,hl,mh,mm,lh (~1e-7, fp32-grade).
// 256 thr / 8 warps (4M x 2N warp tiles of 32x32); 2 CTAs/SM hide sync phases.
template<int P, int NP, bool BT>
__global__ __launch_bounds__(256, 2)
void gemm_split(const float* __restrict__ A, const float* __restrict__ B,
                const float* __restrict__ bias, float* __restrict__ Cout,
                int ldc, int ldb)
{
    constexpr int ROWB  = (P == 2) ? 128 : 256;   // smem bytes per row (all planes)
    constexpr int ATILE = 128 * ROWB;
    constexpr int BTILE = 64 * ROWB;

    __shared__ __align__(1024) char smem[ATILE + BTILE];  // 24 KB or 48 KB static
    const uint32_t sbase = s2u(smem);
    const int tid = threadIdx.x;
    const int w = tid >> 5, l = tid & 31;
    const int m0 = blockIdx.y * 128, n0 = blockIdx.x * 64;
    const int wm = (w >> 1) * 32, wn = (w & 1) * 32;

    float acc[2][4][4];
    #pragma unroll
    for (int a = 0; a < 2; a++)
        #pragma unroll
        for (int b = 0; b < 4; b++)
            #pragma unroll
            for (int c = 0; c < 4; c++) acc[a][b][c] = 0.f;

    float4 bufA[4], bufB[2];

    auto ldg_tiles = [&](int i) {
        const int k0 = i * BK;
        #pragma unroll
        for (int j = 0; j < 4; j++) {
            const int idx = tid * 4 + j;             // 1024 float4s (A)
            const int r = idx >> 3, c = idx & 7;
            bufA[j] = *(const float4*)(A + (size_t)(m0 + r) * KDIM + k0 + c * 4);
        }
        #pragma unroll
        for (int j = 0; j < 2; j++) {
            const int idx = tid * 2 + j;             // 512 float4s (B)
            if (BT) {
                const int kr = idx >> 4, nc = idx & 15;
                bufB[j] = *(const float4*)(B + (size_t)(k0 + kr) * ldb + n0 + nc * 4);
            } else {
                const int r = idx >> 3, c = idx & 7;
                bufB[j] = *(const float4*)(B + (size_t)(n0 + r) * ldb + k0 + c * 4);
            }
        }
    };

    auto swz = [&](int cc, int row) -> uint32_t {
        if (P == 2) return (uint32_t)(cc ^ (row & 7));
        return (uint32_t)((cc & 8) | ((cc & 7) ^ (row & 7)));
    };

    auto splitp = [&](float v, unsigned short* o) {
        __nv_bfloat16 h = __float2bfloat16(v);
        float r1 = v - __bfloat162float(h);
        o[0] = __bfloat16_as_ushort(h);
        if (P == 2) {
            o[1] = __bfloat16_as_ushort(__float2bfloat16(r1));
        } else {
            __nv_bfloat16 m = __float2bfloat16(r1);
            o[1] = __bfloat16_as_ushort(m);
            o[2] = __bfloat16_as_ushort(__float2bfloat16(r1 - __bfloat162float(m)));
        }
    };

    auto sts_tiles = [&]() {
        #pragma unroll
        for (int j = 0; j < 4; j++) {
            const int idx = tid * 4 + j;
            const int r = idx >> 3, c = idx & 7;
            unsigned short sp[4][3];
            splitp(bufA[j].x, sp[0]); splitp(bufA[j].y, sp[1]);
            splitp(bufA[j].z, sp[2]); splitp(bufA[j].w, sp[3]);
            #pragma unroll
            for (int p = 0; p < P; p++) {
                const int cc = p * 4 + (c >> 1);
                const uint32_t ad = (uint32_t)(r * ROWB) + swz(cc, r) * 16u
                                  + (uint32_t)((c & 1) * 8);
                uint2 u;
                u.x = (uint32_t)sp[0][p] | ((uint32_t)sp[1][p] << 16);
                u.y = (uint32_t)sp[2][p] | ((uint32_t)sp[3][p] << 16);
                *(uint2*)(smem + ad) = u;
            }
        }
        #pragma unroll
        for (int j = 0; j < 2; j++) {
            const int idx = tid * 2 + j;
            if (BT) {
                const int kr = idx >> 4, nc = idx & 15;
                const float vv[4] = {bufB[j].x, bufB[j].y, bufB[j].z, bufB[j].w};
                #pragma unroll
                for (int e = 0; e < 4; e++) {
                    const int row = nc * 4 + e;
                    unsigned short sp[3];
                    splitp(vv[e], sp);
                    #pragma unroll
                    for (int p = 0; p < P; p++) {
                        const int cc = p * 4 + (kr >> 3);
                        const uint32_t ad = (uint32_t)ATILE + (uint32_t)(row * ROWB)
                                          + swz(cc, row) * 16u + (uint32_t)((kr & 7) * 2);
                        *(unsigned short*)(smem + ad) = sp[p];
                    }
                }
            } else {
                const int r = idx >> 3, c = idx & 7;
                unsigned short sp[4][3];
                splitp(bufB[j].x, sp[0]); splitp(bufB[j].y, sp[1]);
                splitp(bufB[j].z, sp[2]); splitp(bufB[j].w, sp[3]);
                #pragma unroll
                for (int p = 0; p < P; p++) {
                    const int cc = p * 4 + (c >> 1);
                    const uint32_t ad = (uint32_t)ATILE + (uint32_t)(r * ROWB)
                                      + swz(cc, r) * 16u + (uint32_t)((c & 1) * 8);
                    uint2 u;
                    u.x = (uint32_t)sp[0][p] | ((uint32_t)sp[1][p] << 16);
                    u.y = (uint32_t)sp[2][p] | ((uint32_t)sp[3][p] << 16);
                    *(uint2*)(smem + ad) = u;
                }
            }
        }
    };

    const int rg = ((l >> 3) & 1) * 8 + (l & 7);
    const int ch = l >> 4;
    const uint32_t sA = sbase, sB = sbase + ATILE;

    ldg_tiles(0);
    for (int i = 0; i < NITER; i++) {
        sts_tiles();
        __syncthreads();
        if (i + 1 < NITER) ldg_tiles(i + 1);   // LDG latency overlaps MMA phase

        #pragma unroll
        for (int ps = 0; ps < NP; ps++) {
            const int PA6[6] = {0,0,0,1,1,2}, PB6[6] = {0,1,2,0,1,0};
            const int PA3[3] = {0,0,1},       PB3[3] = {0,1,0};
            const int pa = (NP == 6) ? PA6[ps] : PA3[ps];
            const int pb = (NP == 6) ? PB6[ps] : PB3[ps];
            #pragma unroll
            for (int kt = 0; kt < 2; kt++) {
                uint32_t af[2][4];
                #pragma unroll
                for (int mt = 0; mt < 2; mt++) {
                    const int row = wm + mt * 16 + rg;
                    const int cc = pa * 4 + kt * 2 + ch;
                    const uint32_t ad = sA + (uint32_t)(row * ROWB) + swz(cc, row) * 16u;
                    asm volatile("ldmatrix.sync.aligned.m8n8.x4.shared.b16 {%0,%1,%2,%3}, [%4];\n"
                        : "=r"(af[mt][0]), "=r"(af[mt][1]), "=r"(af[mt][2]), "=r"(af[mt][3])
                        : "r"(ad));
                }
                uint32_t bfr[4][2];
                #pragma unroll
                for (int np = 0; np < 2; np++) {
                    const int row = wn + np * 16 + rg;
                    const int cc = pb * 4 + kt * 2 + ch;
                    const uint32_t ad = sB + (uint32_t)(row * ROWB) + swz(cc, row) * 16u;
                    uint32_t b0, b1, b2, b3;
                    asm volatile("ldmatrix.sync.aligned.m8n8.x4.shared.b16 {%0,%1,%2,%3}, [%4];\n"
                        : "=r"(b0), "=r"(b1), "=r"(b2), "=r"(b3) : "r"(ad));
                    bfr[np * 2 + 0][0] = b0; bfr[np * 2 + 0][1] = b2;
                    bfr[np * 2 + 1][0] = b1; bfr[np * 2 + 1][1] = b3;
                }
                #pragma unroll
                for (int mt = 0; mt < 2; mt++)
                    #pragma unroll
                    for (int nt = 0; nt < 4; nt++)
                        asm volatile(
                            "mma.sync.aligned.m16n8k16.row.col.f32.bf16.bf16.f32 "
                            "{%0,%1,%2,%3}, {%4,%5,%6,%7}, {%8,%9}, {%0,%1,%2,%3};\n"
                            : "+f"(acc[mt][nt][0]), "+f"(acc[mt][nt][1]),
                              "+f"(acc[mt][nt][2]), "+f"(acc[mt][nt][3])
                            : "r"(af[mt][0]), "r"(af[mt][1]), "r"(af[mt][2]), "r"(af[mt][3]),
                              "r"(bfr[nt][0]), "r"(bfr[nt][1]));
            }
        }
        __syncthreads();
    }

    #pragma unroll
    for (int mt = 0; mt < 2; mt++) {
        const int row = m0 + wm + mt * 16 + (l >> 2);
        #pragma unroll
        for (int nt = 0; nt < 4; nt++) {
            const int col = n0 + wn + nt * 8 + (l & 3) * 2;
            float b0 = 0.f, b1 = 0.f;
            if (bias) { b0 = bias[col]; b1 = bias[col + 1]; }
            *(float2*)(Cout + (size_t)row * ldc + col) =
                make_float2(acc[mt][nt][0] + b0, acc[mt][nt][1] + b1);
            *(float2*)(Cout + (size_t)(row + 8) * ldc + col) =
                make_float2(acc[mt][nt][2] + b0, acc[mt][nt][3] + b1);
        }
    }
}

// ---------------- BN stats (unchanged from round 1, which passed) -------------
__global__ void zero_stats_kernel() {
    int t = threadIdx.x;
    if (t < QD) { g_sums[t] = 0.f; g_sqs[t] = 0.f; }
}
__global__ void stats_partial_kernel() {
    const int tid = threadIdx.x;
    const int rowStart = blockIdx.x * 64;
    float s = 0.f, sq = 0.f;
    for (int r = 0; r < 64; r++) {
        const float* row = g_q + (size_t)(rowStart + r) * HQ;
        #pragma unroll
        for (int h = 0; h < HEADS; h++) {
            float v = row[h * QD + tid];
            s += v; sq += v * v;
        }
    }
    atomicAdd(&g_sums[tid], s);
    atomicAdd(&g_sqs[tid], sq);
}
__global__ void finalize_stats_kernel() {
    int t = threadIdx.x;
    if (t < QD) {
        const float invN = 1.0f / (float)(TOK * HEADS);
        float m = g_sums[t] * invN;
        float var = g_sqs[t] * invN - m * m;
        g_mean[t] = m;
        g_rstd[t] = rsqrtf(var + 1e-5f);
    }
}
__global__ void norm_keys_kernel(const float* __restrict__ k0,
                                 const float* __restrict__ k1) {
    const int row = blockIdx.x;
    const int tid = threadIdx.x;
    const float* src = (row < NK) ? (k0 + (size_t)row * HALF)
                                  : (k1 + (size_t)(row - NK) * HALF);
    float* dst = (row < NK) ? (g_k0n + (size_t)row * HALF)
                            : (g_k1n + (size_t)(row - NK) * HALF);
    __shared__ float red[128];
    float v = src[tid];
    red[tid] = v * v;
    __syncthreads();
    for (int s = 64; s > 0; s >>= 1) {
        if (tid < s) red[tid] += red[tid + s];
        __syncthreads();
    }
    float n = sqrtf(red[0]);
    dst[tid] = v / fmaxf(n, 1e-12f);
}

// ---------------- score: BN + L2norm + dots + top4x4 + softmax ----------------
__global__ __launch_bounds__(128)
void score_kernel(const float* __restrict__ gamma,
                  const float* __restrict__ beta) {
    const int u = blockIdx.x;
    const int t = u >> 3;
    const int h = u & 7;
    const int tid = threadIdx.x;

    __shared__ float q0[HALF], q1[HALF];
    __shared__ float red0[128], red1[128];
    __shared__ float s0s[NK], s1s[NK];
    __shared__ float ts0[DTK], ts1[DTK];
    __shared__ int   ti0[DTK], ti1[DTK];
    __shared__ float combS[16];
    __shared__ int   combI[16];
    __shared__ float smx, ssum;

    const float* qrow = g_q + (size_t)t * HQ + h * QD;
    float a = qrow[tid];
    float b = qrow[HALF + tid];
    a = (a - g_mean[tid]) * g_rstd[tid] * gamma[tid] + beta[tid];
    b = (b - g_mean[HALF + tid]) * g_rstd[HALF + tid] * gamma[HALF + tid] + beta[HALF + tid];

    red0[tid] = a * a;
    red1[tid] = b * b;
    __syncthreads();
    for (int s = 64; s > 0; s >>= 1) {
        if (tid < s) { red0[tid] += red0[tid + s]; red1[tid] += red1[tid + s]; }
        __syncthreads();
    }
    float n0 = fmaxf(sqrtf(red0[0]), 1e-12f);
    float n1 = fmaxf(sqrtf(red1[0]), 1e-12f);
    q0[tid] = a / n0;
    q1[tid] = b / n1;
    __syncthreads();

    const int w = tid >> 5, l = tid & 31;
    for (int j = w; j < NK; j += 4) {
        const float* kr0 = g_k0n + j * HALF;
        const float* kr1 = g_k1n + j * HALF;
        float d0 = kr0[l] * q0[l] + kr0[l + 32] * q0[l + 32]
                 + kr0[l + 64] * q0[l + 64] + kr0[l + 96] * q0[l + 96];
        float d1 = kr1[l] * q1[l] + kr1[l + 32] * q1[l + 32]
                 + kr1[l + 64] * q1[l + 64] + kr1[l + 96] * q1[l + 96];
        #pragma unroll
        for (int off = 16; off; off >>= 1) {
            d0 += __shfl_down_sync(0xffffffffu, d0, off);
            d1 += __shfl_down_sync(0xffffffffu, d1, off);
        }
        if (l == 0) { s0s[j] = d0; s1s[j] = d1; }
    }
    __syncthreads();

    if (tid == 0) {
        float vals[NK];
        for (int i = 0; i < NK; i++) vals[i] = s0s[i];
        for (int p = 0; p < DTK; p++) {
            int bi = 0; float bv = -1e30f;
            for (int i = 0; i < NK; i++) if (vals[i] > bv) { bv = vals[i]; bi = i; }
            ts0[p] = bv; ti0[p] = bi; vals[bi] = -1e30f;
        }
    }
    if (tid == 32) {
        float vals[NK];
        for (int i = 0; i < NK; i++) vals[i] = s1s[i];
        for (int p = 0; p < DTK; p++) {
            int bi = 0; float bv = -1e30f;
            for (int i = 0; i < NK; i++) if (vals[i] > bv) { bv = vals[i]; bi = i; }
            ts1[p] = bv; ti1[p] = bi; vals[bi] = -1e30f;
        }
    }
    __syncthreads();

    if (tid < 16) {
        int i = tid >> 2, j = tid & 3;
        combS[tid] = ts0[i] + ts1[j];
        combI[tid] = ti0[i] * NK + ti1[j];
    }
    __syncthreads();
    if (tid == 0) {
        float m = -1e30f;
        for (int k = 0; k < 16; k++) m = fmaxf(m, combS[k]);
        float s = 0.f;
        for (int k = 0; k < 16; k++) s += expf(combS[k] - m);
        smx = m; ssum = s;
    }
    __syncthreads();
    if (tid < 16) {
        g_idx[(size_t)u * 16 + tid] = (unsigned short)combI[tid];
        g_w[(size_t)u * 16 + tid]   = expf(combS[tid] - smx) / ssum;
    }
}

// ---------------- in-place eh -> C transform (in g_q low half) ----------------
__global__ __launch_bounds__(256)
void transformC_kernel() {
    __shared__ float acc[E];
    const int t = blockIdx.x;
    const int tid = threadIdx.x;
    float* ehC = g_q;   // aliased low 4 MB of g_q
    for (int i = tid; i < E; i += 256) acc[i] = 0.f;
    __syncthreads();
    if (tid < NEXP) {
        const int idx = (int)g_idx[(size_t)t * NEXP + tid];
        const float v = ehC[(size_t)t * E + idx];
        const float g = 0.5f * v * (1.0f + erff(v * 0.70710678118654752f));
        atomicAdd(&acc[idx], g * g_w[(size_t)t * NEXP + tid]);
    }
    __syncthreads();
    for (int i = tid; i < E; i += 256) ehC[(size_t)t * E + i] = acc[i];
}

// ---------------- launch -------------------------------------------------------
extern "C" void kernel_launch(void* const* d_in, const int* in_sizes, int n_in,
                              void* d_out, int out_size) {
    const float* hidden = (const float*)d_in[0];   // [2,512,1024]
    const float* Wq     = (const float*)d_in[1];   // [1024,2048]
    const float* bq     = (const float*)d_in[2];   // [2048]
    const float* gamma  = (const float*)d_in[3];   // [256]
    const float* beta   = (const float*)d_in[4];   // [256]
    const float* k0     = (const float*)d_in[5];   // [32,128]
    const float* k1     = (const float*)d_in[6];   // [32,128]
    const float* down   = (const float*)d_in[7];   // [1024,1024]
    const float* up     = (const float*)d_in[8];   // [1024,1024]
    float* out = (float*)d_out;                    // [2,512,1024]

    float* ehC = nullptr;
    cudaGetSymbolAddress((void**)&ehC, g_q);       // eh/C aliases g_q low half

    // q = hidden @ Wq + bq   (6-pass h/m/l split: fp32-grade for routing)
    gemm_split<3, 6, true><<<dim3(HQ / 64, TOK / 128), 256>>>(
        hidden, Wq, bq, ehC /* == g_q base */, HQ, HQ);

    // BN stats + key norms + routing
    zero_stats_kernel<<<1, 256>>>();
    stats_partial_kernel<<<16, 256>>>();
    finalize_stats_kernel<<<1, 256>>>();
    norm_keys_kernel<<<64, 128>>>(k0, k1);
    score_kernel<<<TOK * HEADS, 128>>>(gamma, beta);

    // eh_all = hidden @ down^T  (q is dead now; write into g_q low half)
    gemm_split<2, 3, false><<<dim3(E / 64, TOK / 128), 256>>>(
        hidden, down, nullptr, ehC, E, D);

    // eh -> C in place (gelu * softmax weight, scattered)
    transformC_kernel<<<TOK, 256>>>();

    // out = C @ up
    gemm_split<2, 3, true><<<dim3(O / 64, TOK / 128), 256>>>(
        ehC, up, nullptr, out, O, O);
}

// round 8
// speedup vs baseline: 1.3281x; 1.3281x over previous
#include <cuda_runtime.h>
#include <cuda_bf16.h>
#include <math.h>
#include <stdint.h>

// ---------------- problem constants -----------------------------------------
#define TOK   1024
#define D     1024
#define HQ    2048
#define HEADS 8
#define QD    256
#define HALF  128
#define NK    32
#define DTK   4
#define NEXP  128
#define E     1024
#define O     1024
#define KDIM  1024

// ---------------- scratch (~35 MB; globals proven safe, dynamic smem is not) --
__device__ __align__(256) float g_q[TOK * HQ];               // 8MB; low 4MB -> eh, high 4MB -> C planes
__device__ __align__(256) __nv_bfloat16 g_hid[3 * TOK * D];  // 6MB  (h,m,l planes)
__device__ __align__(256) __nv_bfloat16 g_wqT[3 * HQ * D];   // 12MB (transposed planes)
__device__ __align__(256) __nv_bfloat16 g_dwn[2 * E * D];    // 4MB  (h,l planes)
__device__ __align__(256) __nv_bfloat16 g_upT[2 * O * E];    // 4MB  (transposed planes)
__device__ float g_sums[QD];
__device__ float g_sqs[QD];
__device__ float g_mean[QD];
__device__ float g_rstd[QD];
__device__ float g_k0n[NK * HALF];
__device__ float g_k1n[NK * HALF];
__device__ unsigned short g_idx[TOK * NEXP];
__device__ float g_w[TOK * NEXP];

// ---------------- helpers ----------------------------------------------------
__device__ __forceinline__ uint32_t s2u(const void* p) {
    uint32_t r;
    asm("{ .reg .u64 t; cvta.to.shared.u64 t, %1; cvt.u32.u64 %0, t; }"
        : "=r"(r) : "l"(p));
    return r;
}

// ---------------- plane-precomputed bf16 warp-MMA GEMM ------------------------
// C[m0:+128, n0:+64] = sum_passes A_pa @ B_pb^T.  A planes [P][M][K] bf16,
// B planes [P][N][K] bf16 (already transposed). fp32 out (+bias).
// Static smem, depth-2 cp.async double buffer, 8 warps (4Mx2N of 32x32 tiles).
template<int P, int NP, int BK>
__global__ __launch_bounds__(256, 2)
void gemm_planes(const __nv_bfloat16* __restrict__ A,
                 const __nv_bfloat16* __restrict__ B,
                 const float* __restrict__ bias,
                 float* __restrict__ Cout, int ldc, int aPl, int bPl)
{
    constexpr int CPR   = BK / 8;            // 16B chunks per row per plane
    constexpr int BKB   = BK * 2;            // bytes per row per plane
    constexpr int APL   = 128 * BKB;
    constexpr int BPL   = 64 * BKB;
    constexpr int STAGE = P * (APL + BPL);   // P3/BK16: 18KB; P2/BK32: 24KB
    constexpr int NCHA  = P * 128 * CPR;
    constexpr int NCH   = NCHA + P * 64 * CPR;
    constexpr int NIT   = KDIM / BK;
    constexpr int KT    = BK / 16;

    __shared__ __align__(1024) char smem[2 * STAGE];
    const uint32_t sbase = s2u(smem);
    const int tid = threadIdx.x, w = tid >> 5, l = tid & 31;
    const int m0 = blockIdx.y * 128, n0 = blockIdx.x * 64;
    const int wm = (w >> 1) * 32, wn = (w & 1) * 32;

    float acc[2][4][4];
    #pragma unroll
    for (int a = 0; a < 2; a++)
        #pragma unroll
        for (int b = 0; b < 4; b++)
            #pragma unroll
            for (int c = 0; c < 4; c++) acc[a][b][c] = 0.f;

    auto swz = [](int c, int r) -> int {
        return (BK == 16) ? (c ^ ((r >> 2) & 1)) : (c ^ ((r >> 1) & 3));
    };

    auto issue = [&](int it) {
        const int s = it & 1;
        const int k0 = it * BK;
        const uint32_t sb0 = sbase + (uint32_t)s * STAGE;
        #pragma unroll 2
        for (int id = tid; id < NCH; id += 256) {
            uint32_t dst; const __nv_bfloat16* src;
            if (id < NCHA) {
                const int p = id / (128 * CPR);
                const int rem = id - p * 128 * CPR;
                const int r = rem / CPR, c = rem - r * CPR;
                dst = sb0 + (uint32_t)(p * APL + r * BKB + swz(c, r) * 16);
                src = A + (size_t)p * aPl + (size_t)(m0 + r) * KDIM + k0 + c * 8;
            } else {
                const int id2 = id - NCHA;
                const int p = id2 / (64 * CPR);
                const int rem = id2 - p * 64 * CPR;
                const int r = rem / CPR, c = rem - r * CPR;
                dst = sb0 + (uint32_t)(P * APL + p * BPL + r * BKB + swz(c, r) * 16);
                src = B + (size_t)p * bPl + (size_t)(n0 + r) * KDIM + k0 + c * 8;
            }
            asm volatile("cp.async.cg.shared.global [%0], [%1], 16;\n"
                         :: "r"(dst), "l"(src));
        }
        asm volatile("cp.async.commit_group;\n" ::: "memory");
    };

    const int rg = ((l >> 3) & 1) * 8 + (l & 7);
    const int ch = l >> 4;

    issue(0);
    issue(1);
    for (int i = 0; i < NIT; i++) {
        asm volatile("cp.async.wait_group 1;\n" ::: "memory");
        __syncthreads();
        const uint32_t sb0 = sbase + (uint32_t)(i & 1) * STAGE;

        #pragma unroll
        for (int ps = 0; ps < NP; ps++) {
            const int PA6[6] = {0,0,1,0,1,2}, PB6[6] = {0,1,0,2,1,0};
            const int PA3[3] = {0,0,1},       PB3[3] = {0,1,0};
            const int pa = (NP == 6) ? PA6[ps] : PA3[ps];
            const int pb = (NP == 6) ? PB6[ps] : PB3[ps];
            #pragma unroll
            for (int kt = 0; kt < KT; kt++) {
                uint32_t af[2][4];
                #pragma unroll
                for (int mt = 0; mt < 2; mt++) {
                    const int row = wm + mt * 16 + rg;
                    const int c = kt * 2 + ch;
                    const uint32_t ad = sb0 + (uint32_t)(pa * APL + row * BKB + swz(c, row) * 16);
                    asm volatile("ldmatrix.sync.aligned.m8n8.x4.shared.b16 {%0,%1,%2,%3}, [%4];\n"
                        : "=r"(af[mt][0]), "=r"(af[mt][1]), "=r"(af[mt][2]), "=r"(af[mt][3])
                        : "r"(ad));
                }
                uint32_t bfr[4][2];
                #pragma unroll
                for (int np = 0; np < 2; np++) {
                    const int row = wn + np * 16 + rg;
                    const int c = kt * 2 + ch;
                    const uint32_t ad = sb0 + (uint32_t)(P * APL + pb * BPL + row * BKB + swz(c, row) * 16);
                    uint32_t b0, b1, b2, b3;
                    asm volatile("ldmatrix.sync.aligned.m8n8.x4.shared.b16 {%0,%1,%2,%3}, [%4];\n"
                        : "=r"(b0), "=r"(b1), "=r"(b2), "=r"(b3) : "r"(ad));
                    bfr[np * 2 + 0][0] = b0; bfr[np * 2 + 0][1] = b2;
                    bfr[np * 2 + 1][0] = b1; bfr[np * 2 + 1][1] = b3;
                }
                #pragma unroll
                for (int mt = 0; mt < 2; mt++)
                    #pragma unroll
                    for (int nt = 0; nt < 4; nt++)
                        asm volatile(
                            "mma.sync.aligned.m16n8k16.row.col.f32.bf16.bf16.f32 "
                            "{%0,%1,%2,%3}, {%4,%5,%6,%7}, {%8,%9}, {%0,%1,%2,%3};\n"
                            : "+f"(acc[mt][nt][0]), "+f"(acc[mt][nt][1]),
                              "+f"(acc[mt][nt][2]), "+f"(acc[mt][nt][3])
                            : "r"(af[mt][0]), "r"(af[mt][1]), "r"(af[mt][2]), "r"(af[mt][3]),
                              "r"(bfr[nt][0]), "r"(bfr[nt][1]));
            }
        }
        __syncthreads();
        if (i + 2 < NIT) issue(i + 2);
        else asm volatile("cp.async.commit_group;\n" ::: "memory");
    }

    #pragma unroll
    for (int mt = 0; mt < 2; mt++) {
        const int row = m0 + wm + mt * 16 + (l >> 2);
        #pragma unroll
        for (int nt = 0; nt < 4; nt++) {
            const int col = n0 + wn + nt * 8 + (l & 3) * 2;
            float b0 = 0.f, b1 = 0.f;
            if (bias) { b0 = bias[col]; b1 = bias[col + 1]; }
            *(float2*)(Cout + (size_t)row * ldc + col) =
                make_float2(acc[mt][nt][0] + b0, acc[mt][nt][1] + b1);
            *(float2*)(Cout + (size_t)(row + 8) * ldc + col) =
                make_float2(acc[mt][nt][2] + b0, acc[mt][nt][3] + b1);
        }
    }
}

// ---------------- fp32 -> bf16 plane conversion kernels -----------------------
template<int P>
__global__ void conv_planes(const float* __restrict__ in,
                            __nv_bfloat16* __restrict__ out, int plStride) {
    const int i = blockIdx.x * 256 + threadIdx.x;
    const float v = in[i];
    const __nv_bfloat16 h = __float2bfloat16(v);
    const float r1 = v - __bfloat162float(h);
    const __nv_bfloat16 m = __float2bfloat16(r1);
    out[i] = h;
    out[plStride + i] = m;
    if (P == 3)
        out[2 * plStride + i] = __float2bfloat16(r1 - __bfloat162float(m));
}
// in [KDIM][N] fp32 -> out planes [N][KDIM] bf16
template<int P>
__global__ void convT_planes(const float* __restrict__ in,
                             __nv_bfloat16* __restrict__ out, int N, int plStride) {
    __shared__ float t[32][33];
    const int nx = blockIdx.x * 32, ky = blockIdx.y * 32;
    const int tx = threadIdx.x, ty = threadIdx.y;   // 32 x 8
    #pragma unroll
    for (int j = 0; j < 32; j += 8)
        t[ty + j][tx] = in[(size_t)(ky + ty + j) * N + nx + tx];
    __syncthreads();
    #pragma unroll
    for (int j = 0; j < 32; j += 8) {
        const int n = nx + ty + j;
        const int k = ky + tx;
        const float v = t[tx][ty + j];
        const __nv_bfloat16 h = __float2bfloat16(v);
        const float r1 = v - __bfloat162float(h);
        const __nv_bfloat16 m = __float2bfloat16(r1);
        out[(size_t)n * KDIM + k] = h;
        out[plStride + (size_t)n * KDIM + k] = m;
        if (P == 3)
            out[2 * plStride + (size_t)n * KDIM + k] =
                __float2bfloat16(r1 - __bfloat162float(m));
    }
}

// ---------------- BN stats (unchanged; passing since round 1) -----------------
__global__ void zero_stats_kernel() {
    int t = threadIdx.x;
    if (t < QD) { g_sums[t] = 0.f; g_sqs[t] = 0.f; }
}
__global__ void stats_partial_kernel() {
    const int tid = threadIdx.x;
    const int rowStart = blockIdx.x * 64;
    float s = 0.f, sq = 0.f;
    for (int r = 0; r < 64; r++) {
        const float* row = g_q + (size_t)(rowStart + r) * HQ;
        #pragma unroll
        for (int h = 0; h < HEADS; h++) {
            float v = row[h * QD + tid];
            s += v; sq += v * v;
        }
    }
    atomicAdd(&g_sums[tid], s);
    atomicAdd(&g_sqs[tid], sq);
}
__global__ void finalize_stats_kernel() {
    int t = threadIdx.x;
    if (t < QD) {
        const float invN = 1.0f / (float)(TOK * HEADS);
        float m = g_sums[t] * invN;
        float var = g_sqs[t] * invN - m * m;
        g_mean[t] = m;
        g_rstd[t] = rsqrtf(var + 1e-5f);
    }
}
__global__ void norm_keys_kernel(const float* __restrict__ k0,
                                 const float* __restrict__ k1) {
    const int row = blockIdx.x;
    const int tid = threadIdx.x;
    const float* src = (row < NK) ? (k0 + (size_t)row * HALF)
                                  : (k1 + (size_t)(row - NK) * HALF);
    float* dst = (row < NK) ? (g_k0n + (size_t)row * HALF)
                            : (g_k1n + (size_t)(row - NK) * HALF);
    __shared__ float red[128];
    float v = src[tid];
    red[tid] = v * v;
    __syncthreads();
    for (int s = 64; s > 0; s >>= 1) {
        if (tid < s) red[tid] += red[tid + s];
        __syncthreads();
    }
    float n = sqrtf(red[0]);
    dst[tid] = v / fmaxf(n, 1e-12f);
}

// ---------------- score: BN + L2norm + dots + top4x4 + softmax ----------------
__global__ __launch_bounds__(128)
void score_kernel(const float* __restrict__ gamma,
                  const float* __restrict__ beta) {
    const int u = blockIdx.x;
    const int t = u >> 3;
    const int h = u & 7;
    const int tid = threadIdx.x;

    __shared__ float q0[HALF], q1[HALF];
    __shared__ float red0[128], red1[128];
    __shared__ float s0s[NK], s1s[NK];
    __shared__ float ts0[DTK], ts1[DTK];
    __shared__ int   ti0[DTK], ti1[DTK];
    __shared__ float combS[16];
    __shared__ int   combI[16];
    __shared__ float smx, ssum;

    const float* qrow = g_q + (size_t)t * HQ + h * QD;
    float a = qrow[tid];
    float b = qrow[HALF + tid];
    a = (a - g_mean[tid]) * g_rstd[tid] * gamma[tid] + beta[tid];
    b = (b - g_mean[HALF + tid]) * g_rstd[HALF + tid] * gamma[HALF + tid] + beta[HALF + tid];

    red0[tid] = a * a;
    red1[tid] = b * b;
    __syncthreads();
    for (int s = 64; s > 0; s >>= 1) {
        if (tid < s) { red0[tid] += red0[tid + s]; red1[tid] += red1[tid + s]; }
        __syncthreads();
    }
    float n0 = fmaxf(sqrtf(red0[0]), 1e-12f);
    float n1 = fmaxf(sqrtf(red1[0]), 1e-12f);
    q0[tid] = a / n0;
    q1[tid] = b / n1;
    __syncthreads();

    const int w = tid >> 5, l = tid & 31;
    for (int j = w; j < NK; j += 4) {
        const float* kr0 = g_k0n + j * HALF;
        const float* kr1 = g_k1n + j * HALF;
        float d0 = kr0[l] * q0[l] + kr0[l + 32] * q0[l + 32]
                 + kr0[l + 64] * q0[l + 64] + kr0[l + 96] * q0[l + 96];
        float d1 = kr1[l] * q1[l] + kr1[l + 32] * q1[l + 32]
                 + kr1[l + 64] * q1[l + 64] + kr1[l + 96] * q1[l + 96];
        #pragma unroll
        for (int off = 16; off; off >>= 1) {
            d0 += __shfl_down_sync(0xffffffffu, d0, off);
            d1 += __shfl_down_sync(0xffffffffu, d1, off);
        }
        if (l == 0) { s0s[j] = d0; s1s[j] = d1; }
    }
    __syncthreads();

    if (tid == 0) {
        float vals[NK];
        for (int i = 0; i < NK; i++) vals[i] = s0s[i];
        for (int p = 0; p < DTK; p++) {
            int bi = 0; float bv = -1e30f;
            for (int i = 0; i < NK; i++) if (vals[i] > bv) { bv = vals[i]; bi = i; }
            ts0[p] = bv; ti0[p] = bi; vals[bi] = -1e30f;
        }
    }
    if (tid == 32) {
        float vals[NK];
        for (int i = 0; i < NK; i++) vals[i] = s1s[i];
        for (int p = 0; p < DTK; p++) {
            int bi = 0; float bv = -1e30f;
            for (int i = 0; i < NK; i++) if (vals[i] > bv) { bv = vals[i]; bi = i; }
            ts1[p] = bv; ti1[p] = bi; vals[bi] = -1e30f;
        }
    }
    __syncthreads();

    if (tid < 16) {
        int i = tid >> 2, j = tid & 3;
        combS[tid] = ts0[i] + ts1[j];
        combI[tid] = ti0[i] * NK + ti1[j];
    }
    __syncthreads();
    if (tid == 0) {
        float m = -1e30f;
        for (int k = 0; k < 16; k++) m = fmaxf(m, combS[k]);
        float s = 0.f;
        for (int k = 0; k < 16; k++) s += expf(combS[k] - m);
        smx = m; ssum = s;
    }
    __syncthreads();
    if (tid < 16) {
        g_idx[(size_t)u * 16 + tid] = (unsigned short)combI[tid];
        g_w[(size_t)u * 16 + tid]   = expf(combS[tid] - smx) / ssum;
    }
}

// ---------------- eh -> C bf16 planes (gelu * softmax weight, scattered) ------
__global__ __launch_bounds__(256)
void transformC_kernel(const float* __restrict__ eh,
                       __nv_bfloat16* __restrict__ c0,
                       __nv_bfloat16* __restrict__ c1) {
    __shared__ float acc[E];
    const int t = blockIdx.x;
    const int tid = threadIdx.x;
    for (int i = tid; i < E; i += 256) acc[i] = 0.f;
    __syncthreads();
    if (tid < NEXP) {
        const int idx = (int)g_idx[(size_t)t * NEXP + tid];
        const float v = eh[(size_t)t * E + idx];
        const float g = 0.5f * v * (1.0f + erff(v * 0.70710678118654752f));
        atomicAdd(&acc[idx], g * g_w[(size_t)t * NEXP + tid]);
    }
    __syncthreads();
    for (int i = tid; i < E; i += 256) {
        const float v = acc[i];
        const __nv_bfloat16 h = __float2bfloat16(v);
        c0[(size_t)t * E + i] = h;
        c1[(size_t)t * E + i] = __float2bfloat16(v - __bfloat162float(h));
    }
}

// ---------------- launch -------------------------------------------------------
extern "C" void kernel_launch(void* const* d_in, const int* in_sizes, int n_in,
                              void* d_out, int out_size) {
    const float* hidden = (const float*)d_in[0];   // [2,512,1024]
    const float* Wq     = (const float*)d_in[1];   // [1024,2048]
    const float* bq     = (const float*)d_in[2];   // [2048]
    const float* gamma  = (const float*)d_in[3];   // [256]
    const float* beta   = (const float*)d_in[4];   // [256]
    const float* k0     = (const float*)d_in[5];   // [32,128]
    const float* k1     = (const float*)d_in[6];   // [32,128]
    const float* down   = (const float*)d_in[7];   // [1024,1024]
    const float* up     = (const float*)d_in[8];   // [1024,1024]
    float* out = (float*)d_out;                    // [2,512,1024]

    float* qbuf = nullptr;
    __nv_bfloat16 *hid = nullptr, *wqT = nullptr, *dwn = nullptr, *upT = nullptr;
    cudaGetSymbolAddress((void**)&qbuf, g_q);
    cudaGetSymbolAddress((void**)&hid, g_hid);
    cudaGetSymbolAddress((void**)&wqT, g_wqT);
    cudaGetSymbolAddress((void**)&dwn, g_dwn);
    cudaGetSymbolAddress((void**)&upT, g_upT);
    float* ehBuf = qbuf;                                   // low 4MB of g_q
    __nv_bfloat16* cp0 = (__nv_bfloat16*)(qbuf + TOK * E); // high 4MB of g_q
    __nv_bfloat16* cp1 = cp0 + TOK * E;

    // plane precomputation
    conv_planes<3><<<4096, 256>>>(hidden, hid, TOK * D);
    convT_planes<3><<<dim3(HQ / 32, KDIM / 32), dim3(32, 8)>>>(Wq, wqT, HQ, HQ * D);
    conv_planes<2><<<4096, 256>>>(down, dwn, E * D);
    convT_planes<2><<<dim3(O / 32, KDIM / 32), dim3(32, 8)>>>(up, upT, O, O * E);

    // q = hidden @ Wq + bq (6-pass h/m/l: fp32-grade routing)
    gemm_planes<3, 6, 16><<<dim3(HQ / 64, TOK / 128), 256>>>(
        hid, wqT, bq, qbuf, HQ, TOK * D, HQ * D);

    // BN stats + key norms + routing
    zero_stats_kernel<<<1, 256>>>();
    stats_partial_kernel<<<16, 256>>>();
    finalize_stats_kernel<<<1, 256>>>();
    norm_keys_kernel<<<64, 128>>>(k0, k1);
    score_kernel<<<TOK * HEADS, 128>>>(gamma, beta);

    // eh_all = hidden @ down^T (3-pass h/l); overwrites dead q (low half)
    gemm_planes<2, 3, 32><<<dim3(E / 64, TOK / 128), 256>>>(
        hid, dwn, nullptr, ehBuf, E, TOK * D, E * D);

    // eh -> C planes (gelu * softmax weight, scattered)
    transformC_kernel<<<TOK, 256>>>(ehBuf, cp0, cp1);

    // out = C @ up (3-pass h/l)
    gemm_planes<2, 3, 32><<<dim3(O / 64, TOK / 128), 256>>>(
        cp0, upT, nullptr, out, O, TOK * E, O * E);
}